// round 15
// baseline (speedup 1.0000x reference)
#include <cuda_runtime.h>
#include <cuda_fp16.h>
#include <cstdint>

// ============================================================================
// GCN SAGE + graph-LayerNorm + residual.
// R15: launch-chain reduction — single-kernel scan (ticket/spin last-block),
// finalize folded into consumers, x->fp16 conversion merged into hist kernel.
// 9 launches (was 12). Ticket CSR fill + fused LN1 from R12 retained.
// ============================================================================

#define NN 100000
#define CC 128
#define EMAX 1600000
#define SCAN_BLK 1024

__device__ __half g_aggh[NN * CC];    // aggregated features (fp16)
__device__ __half g_xh[NN * CC];      // x in fp16
__device__ __half g_hpreh[NN * CC];   // pre-LN buffer (fp16), both layers
__device__ double g_stats[4];
__device__ int    g_deg[NN];
__device__ int    g_off[NN + 1];
__device__ int    g_tick[EMAX];       // per-edge slot ticket
__device__ int    g_eidx[EMAX];
__device__ int    g_bsum[SCAN_BLK];
__device__ int    g_scanCount;
__device__ int    g_scanFlag;

// ---------------------------------------------------------------------------
// init0: zero deg / stats / scan flags (must precede hist atomics).
// ---------------------------------------------------------------------------
__global__ void init0_kernel(int nrows) {
    int i = blockIdx.x * blockDim.x + threadIdx.x;
    int stride = gridDim.x * blockDim.x;
    for (int t = i; t < nrows; t += stride) g_deg[t] = 0;
    if (i < 4) g_stats[i] = 0.0;
    if (i == 4) g_scanCount = 0;
    if (i == 5) g_scanFlag = 0;
}

// ---------------------------------------------------------------------------
// histcvt: blocks [0, eBlocks) do degree histogram + tickets;
//          blocks [eBlocks, ...) convert x -> fp16 (runs concurrently).
// ---------------------------------------------------------------------------
__global__ void histcvt_kernel(const int* __restrict__ dst, int E, int nrows,
                               const float* __restrict__ x, long long n4,
                               int eBlocks) {
    if ((int)blockIdx.x < eBlocks) {
        int e = blockIdx.x * 256 + threadIdx.x;
        if (e >= E) return;
        int d = dst[e];
        if ((unsigned)d < (unsigned)nrows)
            g_tick[e] = atomicAdd(&g_deg[d], 1);
    } else {
        long long base = (long long)(blockIdx.x - eBlocks) * 256 + threadIdx.x;
        long long stride = (long long)(gridDim.x - eBlocks) * 256;
        for (long long t = base; t < n4; t += stride) {
            float4 v = ((const float4*)x)[t];
            __half2 h0 = __floats2half2_rn(v.x, v.y);
            __half2 h1 = __floats2half2_rn(v.z, v.w);
            uint2 u;
            u.x = *reinterpret_cast<uint32_t*>(&h0);
            u.y = *reinterpret_cast<uint32_t*>(&h1);
            ((uint2*)g_xh)[t] = u;
        }
    }
}

// ---------------------------------------------------------------------------
// Single-kernel exclusive scan: local scan in regs/smem, ticket counter,
// last-arriving block scans the block sums, flag-release, all blocks add
// their offset. All <=98 blocks are co-resident (1024 thr, 148 SMs) so the
// spin cannot deadlock. Cross-block reads use __ldcg (L2, skips stale L1).
// ---------------------------------------------------------------------------
__global__ __launch_bounds__(SCAN_BLK) void scan_fused_kernel(int nrows, int nblocks) {
    __shared__ int sm[SCAN_BLK];
    __shared__ int s_ticket;
    int t = threadIdx.x;
    int bid = blockIdx.x;
    int i = bid * SCAN_BLK + t;
    int v = (i < nrows) ? g_deg[i] : 0;
    sm[t] = v;
    __syncthreads();
    for (int off = 1; off < SCAN_BLK; off <<= 1) {
        int u = (t >= off) ? sm[t - off] : 0;
        __syncthreads();
        sm[t] += u;
        __syncthreads();
    }
    int excl = sm[t] - v;            // block-local exclusive prefix
    int btotal = sm[SCAN_BLK - 1];
    if (t == 0) {
        g_bsum[bid] = btotal;
        __threadfence();
        s_ticket = atomicAdd(&g_scanCount, 1);
    }
    __syncthreads();

    if (s_ticket == nblocks - 1) {
        // Last block: all g_bsum written. Exclusive-scan them in place.
        int bv = (t < nblocks) ? __ldcg(&g_bsum[t]) : 0;
        __syncthreads();             // sm reuse barrier
        sm[t] = bv;
        __syncthreads();
        for (int off = 1; off < SCAN_BLK; off <<= 1) {
            int u = (t >= off) ? sm[t - off] : 0;
            __syncthreads();
            sm[t] += u;
            __syncthreads();
        }
        if (t < nblocks) g_bsum[t] = sm[t] - bv;
        if (t == SCAN_BLK - 1) g_off[nrows] = sm[t];
        __threadfence();
        if (t == 0) atomicExch(&g_scanFlag, 1);
    } else {
        if (t == 0) {
            while (atomicAdd(&g_scanFlag, 0) == 0) { }
        }
    }
    __syncthreads();
    int boff = __ldcg(&g_bsum[bid]);
    if (i < nrows) g_off[i] = excl + boff;
}

// Atomic-free fill using tickets.
__global__ void fill_kernel(const int* __restrict__ src,
                            const int* __restrict__ dst, int E, int nrows) {
    int e = blockIdx.x * blockDim.x + threadIdx.x;
    if (e >= E) return;
    int d = dst[e];
    int s = src[e];
    if ((unsigned)d >= (unsigned)nrows || (unsigned)s >= (unsigned)nrows) return;
    g_eidx[g_off[d] + g_tick[e]] = s;
}

// ---------------------------------------------------------------------------
// Gather aggregation. layer=0: plain gather from g_xh.
// layer=1: gather from g_hpreh, applying LN1 affine + ReLU on the fly
// (mu/rstd computed inline from g_stats — complete by launch order).
// ---------------------------------------------------------------------------
__global__ __launch_bounds__(256) void agg_kernel(int nrows, int layer,
                                                  const float* __restrict__ gamma,
                                                  const float* __restrict__ beta,
                                                  long long total) {
    int w = (int)(((long long)blockIdx.x * blockDim.x + threadIdx.x) >> 5);
    if (w >= nrows) return;
    int lane = threadIdx.x & 31;
    const __half* __restrict__ h = layer ? g_hpreh : g_xh;
    const __half* base = h + (size_t)lane * 4;

    float4 ga = make_float4(0.f, 0.f, 0.f, 0.f);
    float4 be = make_float4(0.f, 0.f, 0.f, 0.f);
    if (layer) {
        double md = g_stats[0] / (double)total;
        double var = g_stats[1] / (double)total - md * md;
        float mu = (float)md;
        float rstd = (float)rsqrt(var + 1e-5);
        ga = *(const float4*)&gamma[lane * 4];
        be = *(const float4*)&beta[lane * 4];
        // pre-fold: relu((h-mu)*rstd*g + b) = relu(h*(rstd*g) + (b - mu*rstd*g))
        ga.x *= rstd; ga.y *= rstd; ga.z *= rstd; ga.w *= rstd;
        be.x -= mu * ga.x; be.y -= mu * ga.y; be.z -= mu * ga.z; be.w -= mu * ga.w;
    }

    int beg = g_off[w];
    int end = g_off[w + 1];
    float4 acc = make_float4(0.f, 0.f, 0.f, 0.f);

#define LOADROW(rr, f0, f1)                                             \
    float2 f0 = __half22float2(*reinterpret_cast<__half2*>(&rr.x));     \
    float2 f1 = __half22float2(*reinterpret_cast<__half2*>(&rr.y));

#define APPLYLN(f0, f1)                                                 \
    if (layer) {                                                        \
        f0.x = fmaxf(f0.x * ga.x + be.x, 0.f);                          \
        f0.y = fmaxf(f0.y * ga.y + be.y, 0.f);                          \
        f1.x = fmaxf(f1.x * ga.z + be.z, 0.f);                          \
        f1.y = fmaxf(f1.y * ga.w + be.w, 0.f);                          \
    }

    int i = beg;
    for (; i + 4 <= end; i += 4) {
        uint2 r0 = *(const uint2*)(base + (size_t)g_eidx[i + 0] * CC);
        uint2 r1 = *(const uint2*)(base + (size_t)g_eidx[i + 1] * CC);
        uint2 r2 = *(const uint2*)(base + (size_t)g_eidx[i + 2] * CC);
        uint2 r3 = *(const uint2*)(base + (size_t)g_eidx[i + 3] * CC);
        LOADROW(r0, a0, a1) LOADROW(r1, b0, b1)
        LOADROW(r2, c0, c1) LOADROW(r3, d0, d1)
        APPLYLN(a0, a1) APPLYLN(b0, b1) APPLYLN(c0, c1) APPLYLN(d0, d1)
        acc.x += (a0.x + b0.x) + (c0.x + d0.x);
        acc.y += (a0.y + b0.y) + (c0.y + d0.y);
        acc.z += (a1.x + b1.x) + (c1.x + d1.x);
        acc.w += (a1.y + b1.y) + (c1.y + d1.y);
    }
    for (; i < end; ++i) {
        uint2 r0 = *(const uint2*)(base + (size_t)g_eidx[i] * CC);
        LOADROW(r0, a0, a1)
        APPLYLN(a0, a1)
        acc.x += a0.x; acc.y += a0.y; acc.z += a1.x; acc.w += a1.y;
    }
#undef LOADROW
#undef APPLYLN

    float inv = 1.0f / fmaxf((float)(end - beg), 1.0f);
    __half2 o0 = __floats2half2_rn(acc.x * inv, acc.y * inv);
    __half2 o1 = __floats2half2_rn(acc.z * inv, acc.w * inv);
    uint2 u;
    u.x = *reinterpret_cast<uint32_t*>(&o0);
    u.y = *reinterpret_cast<uint32_t*>(&o1);
    ((uint2*)(g_aggh + (size_t)w * CC))[lane] = u;
}

// ---------------------------------------------------------------------------
// TF32 tensor-core fused dual GEMM + LN stats, double-buffered smem.
// layer=0: A1 = g_xh (plain). layer=1: A1 = relu(LN1(g_hpreh)) on the fly.
// ---------------------------------------------------------------------------
__device__ __forceinline__ uint32_t f2tf32(float x) {
    uint32_t r;
    asm("cvt.rna.tf32.f32 %0, %1;" : "=r"(r) : "f"(x));
    return r;
}
__device__ __forceinline__ float tf32f(float x) {
    return __uint_as_float(f2tf32(x));
}

__device__ __forceinline__ void mma_tf32(float& d0, float& d1, float& d2, float& d3,
                                         uint32_t a0, uint32_t a1, uint32_t a2, uint32_t a3,
                                         uint32_t b0, uint32_t b1) {
    asm volatile(
        "mma.sync.aligned.m16n8k8.row.col.f32.tf32.tf32.f32 "
        "{%0,%1,%2,%3}, {%4,%5,%6,%7}, {%8,%9}, {%0,%1,%2,%3};"
        : "+f"(d0), "+f"(d1), "+f"(d2), "+f"(d3)
        : "r"(a0), "r"(a1), "r"(a2), "r"(a3), "r"(b0), "r"(b1));
}

#define LDP 136
#define NTILES 16

__global__ __launch_bounds__(256) void gemm_ln_kernel(
    const float* __restrict__ W0, const float* __restrict__ W1,
    const float* __restrict__ bias,
    const float* __restrict__ lnGamma, const float* __restrict__ lnBeta,
    int statsBase, int nrows, int layer, long long total)
{
    __shared__ float As[2][16][LDP];
    __shared__ float Ws[2][16][LDP];
    __shared__ double red[256];

    int tid = threadIdx.x;
    int lane = tid & 31;
    int wid = tid >> 5;
    int wm = (wid & 3) * 32;
    int wn = (wid >> 2) * 64;
    int g = lane >> 2;
    int c = lane & 3;
    int row0 = blockIdx.x * 128;

    float mu = 0.f, rstd = 0.f;
    if (layer) {
        double md = g_stats[0] / (double)total;
        double var = g_stats[1] / (double)total - md * md;
        mu = (float)md;
        rstd = (float)rsqrt(var + 1e-5);
    }

    float acc[2][8][4];
#pragma unroll
    for (int mt = 0; mt < 2; mt++)
#pragma unroll
        for (int nt = 0; nt < 8; nt++)
#pragma unroll
            for (int q = 0; q < 4; q++) acc[mt][nt][q] = 0.f;

    float4 va[2], wv[2];

    auto load_tile = [&](int t) {
        int phase = t >> 3;
        int k0 = (t & 7) * 16;
        const float* W = phase ? W1 : W0;
        const __half* Ah = phase ? (layer ? g_hpreh : g_xh) : g_aggh;
#pragma unroll
        for (int j = 0; j < 2; ++j) {
            int idx = tid + j * 256;
            int m = idx >> 2;
            int kq = (idx & 3) * 4;
            int gr = row0 + m;
            float4 v = make_float4(0.f, 0.f, 0.f, 0.f);
            if (gr < nrows) {
                uint2 hv = *(const uint2*)(Ah + (size_t)gr * 128 + k0 + kq);
                float2 f0 = __half22float2(*reinterpret_cast<__half2*>(&hv.x));
                float2 f1 = __half22float2(*reinterpret_cast<__half2*>(&hv.y));
                v = make_float4(f0.x, f0.y, f1.x, f1.y);
                if (phase && layer) {
                    float4 gg = *(const float4*)&lnGamma[k0 + kq];
                    float4 bb = *(const float4*)&lnBeta[k0 + kq];
                    v.x = fmaxf((v.x - mu) * rstd * gg.x + bb.x, 0.f);
                    v.y = fmaxf((v.y - mu) * rstd * gg.y + bb.y, 0.f);
                    v.z = fmaxf((v.z - mu) * rstd * gg.z + bb.z, 0.f);
                    v.w = fmaxf((v.w - mu) * rstd * gg.w + bb.w, 0.f);
                }
            }
            va[j] = v;
            int kw = idx >> 5;
            int c4 = idx & 31;
            wv[j] = *(const float4*)(W + (size_t)(k0 + kw) * 128 + c4 * 4);
        }
    };

    auto store_tile = [&](int buf, bool cvtA) {
#pragma unroll
        for (int j = 0; j < 2; ++j) {
            int idx = tid + j * 256;
            int m = idx >> 2;
            int kq = (idx & 3) * 4;
            if (cvtA) {
                As[buf][kq + 0][m] = tf32f(va[j].x);
                As[buf][kq + 1][m] = tf32f(va[j].y);
                As[buf][kq + 2][m] = tf32f(va[j].z);
                As[buf][kq + 3][m] = tf32f(va[j].w);
            } else {
                As[buf][kq + 0][m] = va[j].x;
                As[buf][kq + 1][m] = va[j].y;
                As[buf][kq + 2][m] = va[j].z;
                As[buf][kq + 3][m] = va[j].w;
            }
            int kw = idx >> 5;
            int c4 = idx & 31;
            float4 wt;
            wt.x = tf32f(wv[j].x);
            wt.y = tf32f(wv[j].y);
            wt.z = tf32f(wv[j].z);
            wt.w = tf32f(wv[j].w);
            *(float4*)&Ws[buf][kw][c4 * 4] = wt;
        }
    };

    auto needsCvt = [&](int t) { return (t >> 3) && layer; };

    load_tile(0);
    store_tile(0, needsCvt(0));
    __syncthreads();

    for (int t = 0; t < NTILES; ++t) {
        int buf = t & 1;
        if (t < NTILES - 1) load_tile(t + 1);
#pragma unroll
        for (int ks = 0; ks < 16; ks += 8) {
            uint32_t af[2][4];
#pragma unroll
            for (int mt = 0; mt < 2; mt++) {
                int r = wm + mt * 16 + g;
                af[mt][0] = __float_as_uint(As[buf][ks + c][r]);
                af[mt][1] = __float_as_uint(As[buf][ks + c][r + 8]);
                af[mt][2] = __float_as_uint(As[buf][ks + c + 4][r]);
                af[mt][3] = __float_as_uint(As[buf][ks + c + 4][r + 8]);
            }
            uint32_t bf[8][2];
#pragma unroll
            for (int nt = 0; nt < 8; nt++) {
                int n = wn + nt * 8 + g;
                bf[nt][0] = __float_as_uint(Ws[buf][ks + c][n]);
                bf[nt][1] = __float_as_uint(Ws[buf][ks + c + 4][n]);
            }
#pragma unroll
            for (int mt = 0; mt < 2; mt++)
#pragma unroll
                for (int nt = 0; nt < 8; nt++)
                    mma_tf32(acc[mt][nt][0], acc[mt][nt][1],
                             acc[mt][nt][2], acc[mt][nt][3],
                             af[mt][0], af[mt][1], af[mt][2], af[mt][3],
                             bf[nt][0], bf[nt][1]);
        }
        if (t < NTILES - 1) store_tile(buf ^ 1, needsCvt(t + 1));
        __syncthreads();
    }

    // Epilogue: bias + fp16 store + LN stats
    float s = 0.f, sq = 0.f;
#pragma unroll
    for (int mt = 0; mt < 2; mt++) {
        int r0g = row0 + wm + mt * 16 + g;
#pragma unroll
        for (int nt = 0; nt < 8; nt++) {
            int col = wn + nt * 8 + 2 * c;
            float2 bj = *(const float2*)&bias[col];
            float v0 = acc[mt][nt][0] + bj.x;
            float v1 = acc[mt][nt][1] + bj.y;
            float v2 = acc[mt][nt][2] + bj.x;
            float v3 = acc[mt][nt][3] + bj.y;
            if (r0g < nrows) {
                __half2 hv = __floats2half2_rn(v0, v1);
                *(__half2*)&g_hpreh[(size_t)r0g * 128 + col] = hv;
                s += v0 + v1;
                sq += v0 * v0 + v1 * v1;
            }
            if (r0g + 8 < nrows) {
                __half2 hv = __floats2half2_rn(v2, v3);
                *(__half2*)&g_hpreh[(size_t)(r0g + 8) * 128 + col] = hv;
                s += v2 + v3;
                sq += v2 * v2 + v3 * v3;
            }
        }
    }

    __syncthreads();
    red[tid] = (double)s;
    __syncthreads();
    for (int off = 128; off; off >>= 1) {
        if (tid < off) red[tid] += red[tid + off];
        __syncthreads();
    }
    if (tid == 0) atomicAdd(&g_stats[statsBase + 0], red[0]);
    __syncthreads();
    red[tid] = (double)sq;
    __syncthreads();
    for (int off = 128; off; off >>= 1) {
        if (tid < off) red[tid] += red[tid + off];
        __syncthreads();
    }
    if (tid == 0) atomicAdd(&g_stats[statsBase + 1], red[0]);
}

// ---------------------------------------------------------------------------
// Final LN apply + ReLU + residual -> fp32 out (layer 2 only).
// ---------------------------------------------------------------------------
__global__ void ln_apply_kernel(const float* __restrict__ gamma,
                                const float* __restrict__ beta,
                                int statsBase,
                                const float* __restrict__ residual,
                                float* __restrict__ outExt,
                                long long total)
{
    double cntd = (double)total;
    double mu = g_stats[statsBase + 0] / cntd;
    double var = g_stats[statsBase + 1] / cntd - mu * mu;
    float rstd = (float)rsqrt(var + 1e-5);
    float fmu = (float)mu;

    long long n4 = total >> 2;
    long long i = (long long)blockIdx.x * blockDim.x + threadIdx.x;
    long long stride = (long long)gridDim.x * blockDim.x;

    for (long long t = i; t < n4; t += stride) {
        int cg = (int)(t & 31);
        float4 g = ((const float4*)gamma)[cg];
        float4 b = ((const float4*)beta)[cg];
        uint2 hu = ((const uint2*)g_hpreh)[t];
        float2 h0 = __half22float2(*reinterpret_cast<__half2*>(&hu.x));
        float2 h1 = __half22float2(*reinterpret_cast<__half2*>(&hu.y));
        float4 r = ((const float4*)residual)[t];
        float4 v;
        v.x = fmaxf((h0.x - fmu) * rstd * g.x + b.x, 0.f) + r.x;
        v.y = fmaxf((h0.y - fmu) * rstd * g.y + b.y, 0.f) + r.y;
        v.z = fmaxf((h1.x - fmu) * rstd * g.z + b.z, 0.f) + r.z;
        v.w = fmaxf((h1.y - fmu) * rstd * g.w + b.w, 0.f) + r.w;
        ((float4*)outExt)[t] = v;
    }
}

// ---------------------------------------------------------------------------
extern "C" void kernel_launch(void* const* d_in, const int* in_sizes, int n_in,
                              void* d_out, int out_size)
{
    const float* x   = (const float*)d_in[0];
    const int*   ei  = (const int*)d_in[1];   // int32
    const float* Wl1 = (const float*)d_in[2];
    const float* bl1 = (const float*)d_in[3];
    const float* Wr1 = (const float*)d_in[4];
    const float* g1  = (const float*)d_in[5];
    const float* b1  = (const float*)d_in[6];
    const float* Wl2 = (const float*)d_in[7];
    const float* bl2 = (const float*)d_in[8];
    const float* Wr2 = (const float*)d_in[9];
    const float* g2  = (const float*)d_in[10];
    const float* b2  = (const float*)d_in[11];

    int E = in_sizes[1] / 2;
    int nrows = in_sizes[0] / CC;
    long long total = (long long)nrows * CC;

    const int* src = ei;
    const int* dst = ei + E;

    int eBlocks    = (E + 255) / 256;
    int cvtBlocks  = 2048;
    int aggBlocks  = (nrows + 7) / 8;
    int gemmBlocks = (nrows + 127) / 128;
    int lnBlocks   = (int)((total / 4 + 255) / 256);
    int scanBlocks = (nrows + SCAN_BLK - 1) / SCAN_BLK;   // 98 <= SMs (co-resident)

    // ---- CSR build + x->half (overlapped) ----
    init0_kernel<<<512, 256>>>(nrows);
    histcvt_kernel<<<eBlocks + cvtBlocks, 256>>>(dst, E, nrows, x, total / 4, eBlocks);
    scan_fused_kernel<<<scanBlocks, SCAN_BLK>>>(nrows, scanBlocks);
    fill_kernel<<<eBlocks, 256>>>(src, dst, E, nrows);

    // ---- Layer 1 ----
    agg_kernel<<<aggBlocks, 256>>>(nrows, 0, nullptr, nullptr, total);
    gemm_ln_kernel<<<gemmBlocks, 256>>>(Wl1, Wr1, bl1, nullptr, nullptr, 0, nrows, 0, total);

    // ---- Layer 2 (LN1+ReLU fused into consumers; stats read inline) ----
    agg_kernel<<<aggBlocks, 256>>>(nrows, 1, g1, b1, total);
    gemm_ln_kernel<<<gemmBlocks, 256>>>(Wl2, Wr2, bl2, g1, b1, 2, nrows, 1, total);
    ln_apply_kernel<<<lnBlocks, 256>>>(g2, b2, 2, x, (float*)d_out, total);
}